// round 2
// baseline (speedup 1.0000x reference)
#include <cuda_runtime.h>
#include <cuda_bf16.h>
#include <math.h>

// Problem constants (from setup_inputs): E=4096, N=1024, IN=OUT=256, q=1.0
#define EMAX   4096
#define NNODES 1024
#define OUTF   256

// Scratch (no allocations allowed)
__device__ float g_h[EMAX * OUTF];      // h = x @ W^T        (4 MB)
__device__ float g_t[NNODES * OUTF];    // t = U^T (dinv*h)   (1 MB)
__device__ int   g_deg[EMAX];           // exact |L| row sums (integers)
__device__ int   g_dirflag;             // 0=int32, 1=uint8, 2=float32

// ---------------------------------------------------------------------------
// 0. detect is_directed dtype (bool marshalling is undocumented).
//    Scans only the first E bytes (valid under every candidate layout):
//      int32  0/1 -> bytes at pos%4!=0 are all zero
//      float32 1.0f -> bytes 0x80 / 0x3f appear
//      uint8  0/1 -> nonzero bytes at unaligned positions, never 0x3f/0x80
// ---------------------------------------------------------------------------
__global__ void detect_kernel(const unsigned char* __restrict__ dirs, int E) {
    __shared__ int nz_unaligned, f32_marker;
    if (threadIdx.x == 0) { nz_unaligned = 0; f32_marker = 0; }
    __syncthreads();
    int local_nz = 0, local_f32 = 0;
    for (int i = threadIdx.x; i < E; i += blockDim.x) {
        unsigned char b = dirs[i];
        if ((i & 3) != 0 && b) local_nz = 1;
        if (b == 0x3f || b == 0x80) local_f32 = 1;
    }
    if (local_nz)  atomicOr(&nz_unaligned, 1);
    if (local_f32) atomicOr(&f32_marker, 1);
    __syncthreads();
    if (threadIdx.x == 0)
        g_dirflag = f32_marker ? 2 : (nz_unaligned ? 1 : 0);
}

__device__ __forceinline__ bool get_dir(const void* dirs, int e) {
    int f = g_dirflag;
    if (f == 0) return ((const int*)dirs)[e] != 0;
    if (f == 1) return ((const unsigned char*)dirs)[e] != 0;
    return ((const float*)dirs)[e] != 0.f;
}

// ---------------------------------------------------------------------------
// 1. zero scratch (t and deg)
// ---------------------------------------------------------------------------
__global__ void zero_kernel() {
    int i = blockIdx.x * blockDim.x + threadIdx.x;
    int nt = NNODES * OUTF;
    for (int j = i; j < nt; j += gridDim.x * blockDim.x) g_t[j] = 0.f;
    if (i < EMAX) g_deg[i] = 0;
}

// ---------------------------------------------------------------------------
// 2. GEMM: h[e][o] = sum_k x[e][k] * W[o][k]   (both K-major, "NT")
//    BM=BN=64, BK=16, 256 threads, 4x4 register tile per thread
// ---------------------------------------------------------------------------
__global__ void gemm_kernel(const float* __restrict__ X,
                            const float* __restrict__ W,
                            int E, int K, int O) {
    __shared__ float As[64][17];
    __shared__ float Bs[64][17];
    const int tid = threadIdx.x;
    const int tx = tid & 15;          // 0..15  -> N sub-tile
    const int ty = tid >> 4;          // 0..15  -> M sub-tile
    const int bm = blockIdx.x * 64;
    const int bn = blockIdx.y * 64;

    const int lr = tid >> 2;          // 0..63 load row
    const int lc = (tid & 3) * 4;     // 0,4,8,12 load col

    float acc[4][4] = {};

    for (int k0 = 0; k0 < K; k0 += 16) {
        float4 av = *(const float4*)&X[(bm + lr) * K + k0 + lc];
        float4 bv = *(const float4*)&W[(bn + lr) * K + k0 + lc];
        As[lr][lc + 0] = av.x; As[lr][lc + 1] = av.y;
        As[lr][lc + 2] = av.z; As[lr][lc + 3] = av.w;
        Bs[lr][lc + 0] = bv.x; Bs[lr][lc + 1] = bv.y;
        Bs[lr][lc + 2] = bv.z; Bs[lr][lc + 3] = bv.w;
        __syncthreads();
        #pragma unroll
        for (int kk = 0; kk < 16; kk++) {
            float a[4], b[4];
            #pragma unroll
            for (int i = 0; i < 4; i++) a[i] = As[ty * 4 + i][kk];
            #pragma unroll
            for (int j = 0; j < 4; j++) b[j] = Bs[tx * 4 + j][kk];
            #pragma unroll
            for (int i = 0; i < 4; i++)
                #pragma unroll
                for (int j = 0; j < 4; j++)
                    acc[i][j] = fmaf(a[i], b[j], acc[i][j]);
        }
        __syncthreads();
    }
    #pragma unroll
    for (int i = 0; i < 4; i++) {
        float* row = &g_h[(bm + ty * 4 + i) * O + bn + tx * 4];
        #pragma unroll
        for (int j = 0; j < 4; j++) row[j] = acc[i][j];
    }
}

// ---------------------------------------------------------------------------
// 3. exact deg: deg[e] = sum_f | [se==sf] + [de==df] - [se==df] - [de==sf] |
//    Edges packed 10+10 bits in smem; grid.y splits the f range.
// ---------------------------------------------------------------------------
#define FCHUNK 512
__global__ void deg_kernel(const int* __restrict__ ei, int E) {
    __shared__ unsigned int pk[FCHUNK];
    const int tid = threadIdx.x;
    const int e  = blockIdx.x * blockDim.x + tid;
    const int f0 = blockIdx.y * FCHUNK;

    for (int i = tid; i < FCHUNK; i += blockDim.x) {
        int f = f0 + i;
        pk[i] = (unsigned)ei[f] | ((unsigned)ei[E + f] << 10);
    }
    __syncthreads();

    const int es = ei[e];
    const int ed = ei[E + e];
    int deg = 0;
    #pragma unroll 8
    for (int i = 0; i < FCHUNK; i++) {
        unsigned w = pk[i];
        int fs = (int)(w & 1023u);
        int fd = (int)((w >> 10) & 1023u);
        int m = (es == fs) + (ed == fd) - (es == fd) - (ed == fs);
        deg += abs(m);
    }
    atomicAdd(&g_deg[e], deg);
}

// ---------------------------------------------------------------------------
// 4. scatter: t[src_f] += s_f*dinv_f*h[f],  t[dst_f] -= ...
//    one thread per (edge, 4-column group)
// ---------------------------------------------------------------------------
__global__ void scatter_kernel(const int* __restrict__ ei,
                               const void* __restrict__ dirs,
                               int E) {
    int idx = blockIdx.x * blockDim.x + threadIdx.x;
    int e = idx >> 6;                  // OUTF/4 = 64 groups per edge
    int c = (idx & 63) << 2;
    if (e >= E) return;
    int s = ei[e], d = ei[E + e];
    float sign = get_dir(dirs, e) ? -1.f : 1.f;   // global flip vs ref: harmless (L ~ s_e*s_f)
    int dg = g_deg[e];
    float coef = sign * (dg > 0 ? rsqrtf((float)dg) : 0.f);
    float4 h = *(const float4*)&g_h[e * OUTF + c];
    float vx = coef * h.x, vy = coef * h.y, vz = coef * h.z, vw = coef * h.w;
    float* ts = &g_t[s * OUTF + c];
    float* td = &g_t[d * OUTF + c];
    atomicAdd(ts + 0,  vx); atomicAdd(ts + 1,  vy);
    atomicAdd(ts + 2,  vz); atomicAdd(ts + 3,  vw);
    atomicAdd(td + 0, -vx); atomicAdd(td + 1, -vy);
    atomicAdd(td + 2, -vz); atomicAdd(td + 3, -vw);
}

// ---------------------------------------------------------------------------
// 5. gather: out[e] = s_e*dinv_e*(t[src_e] - t[dst_e])
// ---------------------------------------------------------------------------
__global__ void gather_kernel(const int* __restrict__ ei,
                              const void* __restrict__ dirs,
                              float* __restrict__ out, int E) {
    int idx = blockIdx.x * blockDim.x + threadIdx.x;
    int e = idx >> 6;
    int c = (idx & 63) << 2;
    if (e >= E) return;
    int s = ei[e], d = ei[E + e];
    float sign = get_dir(dirs, e) ? -1.f : 1.f;
    int dg = g_deg[e];
    float coef = sign * (dg > 0 ? rsqrtf((float)dg) : 0.f);
    float4 a = *(const float4*)&g_t[s * OUTF + c];
    float4 b = *(const float4*)&g_t[d * OUTF + c];
    float4 o;
    o.x = coef * (a.x - b.x);
    o.y = coef * (a.y - b.y);
    o.z = coef * (a.z - b.z);
    o.w = coef * (a.w - b.w);
    *(float4*)&out[e * OUTF + c] = o;
}

// ---------------------------------------------------------------------------
extern "C" void kernel_launch(void* const* d_in, const int* in_sizes, int n_in,
                              void* d_out, int out_size) {
    const float* x    = (const float*)d_in[0];
    const float* W    = (const float*)d_in[1];
    const int*   ei   = (const int*)d_in[2];
    const void*  dirs = d_in[3];
    float* out = (float*)d_out;

    const int E = in_sizes[3];            // 4096
    const int K = in_sizes[0] / E;        // 256 (IN)
    const int O = in_sizes[1] / K;        // 256 (OUT)

    detect_kernel<<<1, 256>>>((const unsigned char*)dirs, E);
    zero_kernel<<<(NNODES * OUTF) / 256, 256>>>();
    gemm_kernel<<<dim3(E / 64, O / 64), 256>>>(x, W, E, K, O);
    deg_kernel<<<dim3(E / 256, E / FCHUNK), 256>>>(ei, E);
    int groups = E * (OUTF / 4);
    scatter_kernel<<<(groups + 255) / 256, 256>>>(ei, dirs, E);
    gather_kernel<<<(groups + 255) / 256, 256>>>(ei, dirs, out, E);
}

// round 10
// speedup vs baseline: 1.3833x; 1.3833x over previous
#include <cuda_runtime.h>
#include <cuda_bf16.h>
#include <math.h>

// E=4096, N=1024, IN=OUT=256, q=1.0 (phase = -1, real => L = real Gram of signed incidence)
#define EMAX   4096
#define NNODES 1024
#define OUTF   256

typedef unsigned long long ull;

__device__ float g_t[NNODES * OUTF];    // t = U^T (coef*h)  (1 MB, L2-resident)
__device__ int   g_cnt[NNODES];         // non-self-loop endpoint counts
__device__ int   g_dirflag;             // 0=int32, 1=uint8, 2=float32

// ---------------------------------------------------------------------------
// packed f32x2 helpers (Blackwell FFMA2 — PTX-only, per SASS_QUICKREF)
// ---------------------------------------------------------------------------
__device__ __forceinline__ void fma2(ull& d, ull a, ull b) {
    asm("fma.rn.f32x2 %0, %1, %2, %0;" : "+l"(d) : "l"(a), "l"(b));
}
__device__ __forceinline__ void unpack2(float& lo, float& hi, ull v) {
    asm("mov.b64 {%0, %1}, %2;" : "=f"(lo), "=f"(hi) : "l"(v));
}

// ---------------------------------------------------------------------------
// dirs dtype sniffer (bool marshalling undocumented) — proven working in R2
// ---------------------------------------------------------------------------
__device__ __forceinline__ bool get_dir(const void* dirs, int e) {
    int f = g_dirflag;
    if (f == 0) return ((const int*)dirs)[e] != 0;
    if (f == 1) return ((const unsigned char*)dirs)[e] != 0;
    return ((const float*)dirs)[e] != 0.f;
}

// coef_e = sign_e / sqrt(deg_e), deg_e = cnt[s]+cnt[d]; 0 for self-loops.
// (deg identity: for non-self-loops the +/- endpoint-coincidence terms can
//  never cancel, so |sum| == sum of abs => deg[e] = cnt[src]+cnt[dst].)
__device__ __forceinline__ float edge_coef(const int* ei, const void* dirs,
                                           int E, int e, int& s, int& d) {
    s = ei[e]; d = ei[E + e];
    if (s == d) return 0.f;
    float sign = get_dir(dirs, e) ? -1.f : 1.f;   // global flip vs ref: L ~ s_e*s_f, invariant
    return sign * rsqrtf((float)(g_cnt[s] + g_cnt[d]));
}

// ---------------------------------------------------------------------------
// 1. init: zero g_t (all blocks), histogram + dtype detect (block 0)
// ---------------------------------------------------------------------------
__global__ void init_kernel(const int* __restrict__ ei,
                            const unsigned char* __restrict__ dirs, int E) {
    int gid = blockIdx.x * blockDim.x + threadIdx.x;
    ((float4*)g_t)[gid] = make_float4(0.f, 0.f, 0.f, 0.f);

    if (blockIdx.x == 0) {
        __shared__ int cnt[NNODES];
        __shared__ int nz, f32m;
        if (threadIdx.x == 0) { nz = 0; f32m = 0; }
        for (int i = threadIdx.x; i < NNODES; i += 256) cnt[i] = 0;
        __syncthreads();
        int lnz = 0, lf = 0;
        for (int e = threadIdx.x; e < E; e += 256) {
            int s = ei[e], d = ei[E + e];
            if (s != d) { atomicAdd(&cnt[s], 1); atomicAdd(&cnt[d], 1); }
            unsigned char b = dirs[e];
            if ((e & 3) != 0 && b) lnz = 1;
            if (b == 0x3f || b == 0x80) lf = 1;
        }
        if (lnz) atomicOr(&nz, 1);
        if (lf)  atomicOr(&f32m, 1);
        __syncthreads();
        for (int i = threadIdx.x; i < NNODES; i += 256) g_cnt[i] = cnt[i];
        if (threadIdx.x == 0) g_dirflag = f32m ? 2 : (nz ? 1 : 0);
    }
}

// ---------------------------------------------------------------------------
// 2. fused GEMM + scatter, FFMA2 mainloop:
//    As2 holds A k-major DUPLICATED (a,a) so splat operands are one LDS.64;
//    Bs  holds B k-major so (b_j,b_j+1) pairs are aligned b64 operands.
//    Per kk: 3x LDS.128 + 8x fma.rn.f32x2  (was 2x LDS.128 + 16x FFMA)
//    epilogue: g_t[src_e] += coef_e*acc,  g_t[dst_e] -= coef_e*acc  (RED.F32)
// ---------------------------------------------------------------------------
__global__ void __launch_bounds__(256)
gemm_scatter_kernel(const float* __restrict__ X,
                    const float* __restrict__ W,
                    const int* __restrict__ ei,
                    const void* __restrict__ dirs,
                    int E, int K, int O) {
    __shared__ float As2[16][136];  // [k][2*row] duplicated; 544B stride (16B-mult)
    __shared__ float Bs[16][68];    // [k][row];             272B stride (16B-mult)
    const int tid = threadIdx.x;
    const int tx = tid & 15;           // N sub-tile
    const int ty = tid >> 4;           // M sub-tile
    const int bm = blockIdx.x * 64;
    const int bn = blockIdx.y * 64;
    const int lr = tid >> 2;           // 0..63 load row
    const int lc = (tid & 3) * 4;      // 0,4,8,12 load col

    ull acc2[4][2] = {};               // [i][j-pair], 16 f32 accumulators

    for (int k0 = 0; k0 < K; k0 += 16) {
        float4 av = *(const float4*)&X[(bm + lr) * K + k0 + lc];
        float4 bv = *(const float4*)&W[(bn + lr) * K + k0 + lc];
        *(float2*)&As2[lc + 0][2 * lr] = make_float2(av.x, av.x);
        *(float2*)&As2[lc + 1][2 * lr] = make_float2(av.y, av.y);
        *(float2*)&As2[lc + 2][2 * lr] = make_float2(av.z, av.z);
        *(float2*)&As2[lc + 3][2 * lr] = make_float2(av.w, av.w);
        Bs[lc + 0][lr] = bv.x; Bs[lc + 1][lr] = bv.y;
        Bs[lc + 2][lr] = bv.z; Bs[lc + 3][lr] = bv.w;
        __syncthreads();
        #pragma unroll
        for (int kk = 0; kk < 16; kk++) {
            ulonglong2 a01 = *(const ulonglong2*)&As2[kk][ty * 8];      // splats i=0,1
            ulonglong2 a23 = *(const ulonglong2*)&As2[kk][ty * 8 + 4];  // splats i=2,3
            ulonglong2 bb  = *(const ulonglong2*)&Bs[kk][tx * 4];       // (b0,b1),(b2,b3)
            fma2(acc2[0][0], a01.x, bb.x); fma2(acc2[0][1], a01.x, bb.y);
            fma2(acc2[1][0], a01.y, bb.x); fma2(acc2[1][1], a01.y, bb.y);
            fma2(acc2[2][0], a23.x, bb.x); fma2(acc2[2][1], a23.x, bb.y);
            fma2(acc2[3][0], a23.y, bb.x); fma2(acc2[3][1], a23.y, bb.y);
        }
        __syncthreads();
    }

    // epilogue: scatter into node accumulator
    #pragma unroll
    for (int i = 0; i < 4; i++) {
        int e = bm + ty * 4 + i, s, d;
        float coef = edge_coef(ei, dirs, E, e, s, d);
        float* ts = &g_t[s * OUTF + bn + tx * 4];
        float* td = &g_t[d * OUTF + bn + tx * 4];
        float v0, v1, v2, v3;
        unpack2(v0, v1, acc2[i][0]);
        unpack2(v2, v3, acc2[i][1]);
        float w0 = coef * v0, w1 = coef * v1, w2 = coef * v2, w3 = coef * v3;
        atomicAdd(ts + 0,  w0); atomicAdd(ts + 1,  w1);
        atomicAdd(ts + 2,  w2); atomicAdd(ts + 3,  w3);
        atomicAdd(td + 0, -w0); atomicAdd(td + 1, -w1);
        atomicAdd(td + 2, -w2); atomicAdd(td + 3, -w3);
    }
}

// ---------------------------------------------------------------------------
// 3. gather: out[e] = coef_e * (t[src_e] - t[dst_e])
// ---------------------------------------------------------------------------
__global__ void gather_kernel(const int* __restrict__ ei,
                              const void* __restrict__ dirs,
                              float* __restrict__ out, int E) {
    int idx = blockIdx.x * blockDim.x + threadIdx.x;
    int e = idx >> 6;                  // OUTF/4 = 64 col-groups per edge
    int c = (idx & 63) << 2;
    int s, d;
    float coef = edge_coef(ei, dirs, E, e, s, d);
    float4 a = *(const float4*)&g_t[s * OUTF + c];
    float4 b = *(const float4*)&g_t[d * OUTF + c];
    float4 o;
    o.x = coef * (a.x - b.x);
    o.y = coef * (a.y - b.y);
    o.z = coef * (a.z - b.z);
    o.w = coef * (a.w - b.w);
    *(float4*)&out[e * OUTF + c] = o;
}

// ---------------------------------------------------------------------------
extern "C" void kernel_launch(void* const* d_in, const int* in_sizes, int n_in,
                              void* d_out, int out_size) {
    const float* x    = (const float*)d_in[0];
    const float* W    = (const float*)d_in[1];
    const int*   ei   = (const int*)d_in[2];
    const void*  dirs = d_in[3];
    float* out = (float*)d_out;

    const int E = in_sizes[3];            // 4096
    const int K = in_sizes[0] / E;        // 256
    const int O = in_sizes[1] / K;        // 256

    init_kernel<<<(NNODES * OUTF / 4) / 256, 256>>>(ei, (const unsigned char*)dirs, E);
    gemm_scatter_kernel<<<dim3(E / 64, O / 64), 256>>>(x, W, ei, dirs, E, K, O);
    gather_kernel<<<E * (OUTF / 4) / 256, 256>>>(ei, dirs, out, E);
}